// round 12
// baseline (speedup 1.0000x reference)
#include <cuda_runtime.h>
#include <cuda_bf16.h>
#include <cstdint>

typedef unsigned int u32;

#define LSEQ 2048
#define DIMV 32
#define CHK 64
#define NCH 32
#define THREADS 256
#define NPAIRS 496
#define OUTW 528

#define STAGE 8448                  // 65 rows x 128 B, padded to 66 rows
#define SMEMSZ 16896                // 2 stages; also exactly C[64][66] f32

__device__ __forceinline__ u32 smem_u32(const void* p) {
    u32 a;
    asm("{ .reg .u64 t; cvta.to.shared.u64 t, %1; cvt.u32.u64 %0, t; }" : "=r"(a) : "l"(p));
    return a;
}
__device__ __forceinline__ u32 cvtpack(float lo, float hi) {   // low half = lo
    u32 r;
    asm("cvt.rn.bf16x2.f32 %0, %1, %2;" : "=r"(r) : "f"(hi), "f"(lo));
    return r;
}
__device__ __forceinline__ void sts_b32(u32 a, u32 v) {
    asm volatile("st.shared.b32 [%0], %1;" ::"r"(a), "r"(v));
}
__device__ __forceinline__ void ldsm4t(u32 addr, u32* r) {
    asm volatile("ldmatrix.sync.aligned.m8n8.x4.trans.shared.b16 {%0,%1,%2,%3}, [%4];"
                 : "=r"(r[0]), "=r"(r[1]), "=r"(r[2]), "=r"(r[3]) : "r"(addr));
}
__device__ __forceinline__ void mma16816(float* d, const u32* a, u32 b0, u32 b1) {
    asm volatile(
        "mma.sync.aligned.m16n8k16.row.col.f32.bf16.bf16.f32 "
        "{%0,%1,%2,%3}, {%4,%5,%6,%7}, {%8,%9}, {%0,%1,%2,%3};"
        : "+f"(d[0]), "+f"(d[1]), "+f"(d[2]), "+f"(d[3])
        : "r"(a[0]), "r"(a[1]), "r"(a[2]), "r"(a[3]), "r"(b0), "r"(b1));
}

__global__ __launch_bounds__(THREADS, 3) void logsig_mma(const float* __restrict__ x,
                                                         float* __restrict__ out) {
    __shared__ __align__(128) char smem[SMEMSZ];
    __shared__ float x0s[DIMV], l1s[DIMV];

    const int b = blockIdx.x, tid = threadIdx.x, w = tid >> 5, lane = tid & 31;
    const int mh = w & 1, nh = (w >> 1) & 1, kh = w >> 2;   // warp = (m-half, n-half, k-half)
    const int e = lane >> 4, p = lane & 15;                 // dim-pair p, k-subgroup e
    const bool bnd = (w == 7) && (e == 1);                  // handles tile row 64
    const float* gx = x + (size_t)b * LSEQ * DIMV;
    const u32 sbase = smem_u32(smem);

    // ---- prefetch: 8 (+2 boundary) floats: rows kb..kb+3 of chunk, dims 2p,2p+1 ----
    const int kb = 8 * w + 4 * e;
    auto load = [&](float* v, int c) {
        const float* basep = gx + (size_t)(c * CHK + kb) * DIMV + 2 * p;
#pragma unroll
        for (int j = 0; j < 4; j++) {
            float2 t = *(const float2*)(basep + j * DIMV);
            v[2 * j] = t.x; v[2 * j + 1] = t.y;
        }
        if (bnd) {
            int row = c * CHK + 64;
            if (row < LSEQ) {
                float2 t = *(const float2*)(gx + (size_t)row * DIMV + 2 * p);
                v[8] = t.x; v[9] = t.y;
            } else { v[8] = 0.f; v[9] = 0.f; }
        }
    };

    // ---- convert one (k,dim-pair) to hi/lo bf16x2 and store swizzled ----
    auto cvt_sts = [&](float v0, float v1, int k, u32 tb) {
        u32 h = cvtpack(v0, v1);
        float f0 = __uint_as_float(h << 16);
        float f1 = __uint_as_float(h & 0xFFFF0000u);
        u32 l = cvtpack(v0 - f0, v1 - f1);
        u32 rowb = tb + (u32)k * 128u + 4u * (u32)(p & 3);
        u32 sw = (u32)k & 7u;
        sts_b32(rowb + ((((u32)p >> 2) ^ sw) << 4), h);            // hi: unit p/4
        sts_b32(rowb + (((4u + ((u32)p >> 2)) ^ sw) << 4), l);     // lo: unit 4+p/4
    };

    float acc[8][4];
#pragma unroll
    for (int i = 0; i < 8; i++)
#pragma unroll
        for (int r = 0; r < 4; r++) acc[i][r] = 0.f;

    float vA[10], vB[10];
    load(vA, 0);

    // ---- one iteration ----
    auto iter = [&](int c, float* vc, float* vn) {
        if (c + 1 < NCH) load(vn, c + 1);           // LDGs issued early, consumed next iter
        const u32 tb = sbase + (u32)(c & 1) * STAGE;
#pragma unroll
        for (int j = 0; j < 4; j++) cvt_sts(vc[2 * j], vc[2 * j + 1], kb + j, tb);
        if (bnd) cvt_sts(vc[8], vc[9], 64, tb);
        __syncthreads();                             // single barrier per chunk

        // ldsm + mma: this warp's k-half (2 k16 blocks)
#pragma unroll
        for (int qi = 0; qi < 2; qi++) {
            const int k0 = (kh * 2 + qi) * 16;
            u32 afr[2][4], bfr[2][4];
#pragma unroll
            for (int tm = 0; tm < 2; tm++) {        // A: rows k0+.., units m-quadrant
                u32 row = (u32)(k0 + ((lane >> 4) << 3) + (lane & 7));
                u32 unit = (u32)(mh * 4 + tm * 2 + ((lane >> 3) & 1));
                ldsm4t(tb + row * 128u + ((unit ^ (row & 7u)) << 4), afr[tm]);
            }
#pragma unroll
            for (int tn = 0; tn < 2; tn++) {        // B: rows k0+1+.., units n-quadrant
                u32 row = (u32)(k0 + 1 + (((lane >> 3) & 1) << 3) + (lane & 7));
                u32 unit = (u32)(nh * 4 + tn * 2 + ((lane >> 4) & 1));
                ldsm4t(tb + row * 128u + ((unit ^ (row & 7u)) << 4), bfr[tn]);
            }
#pragma unroll
            for (int tm = 0; tm < 2; tm++)
#pragma unroll
                for (int tn = 0; tn < 2; tn++) {
                    mma16816(acc[tm * 4 + tn * 2 + 0], afr[tm], bfr[tn][0], bfr[tn][1]);
                    mma16816(acc[tm * 4 + tn * 2 + 1], afr[tm], bfr[tn][2], bfr[tn][3]);
                }
        }
    };

#pragma unroll 1
    for (int c = 0; c < NCH; c += 2) {
        iter(c, vA, vB);
        iter(c + 1, vB, vA);
    }

    __syncthreads();                                 // all mma reads done before C overwrite
    // ---- k-half reduction into smem C[64][66] ----
    float* C = (float*)smem;
    if (kh == 0) {
#pragma unroll
        for (int t = 0; t < 8; t++) {
            int tm = t >> 2, tn8 = t & 3;
#pragma unroll
            for (int r = 0; r < 4; r++) {
                int m = mh * 32 + tm * 16 + (lane >> 2) + (r >> 1) * 8;
                int n = nh * 32 + tn8 * 8 + (lane & 3) * 2 + (r & 1);
                C[m * 66 + n] = acc[t][r];
            }
        }
    }
    __syncthreads();
    if (kh == 1) {
#pragma unroll
        for (int t = 0; t < 8; t++) {
            int tm = t >> 2, tn8 = t & 3;
#pragma unroll
            for (int r = 0; r < 4; r++) {
                int m = mh * 32 + tm * 16 + (lane >> 2) + (r >> 1) * 8;
                int n = nh * 32 + tn8 * 8 + (lane & 3) * 2 + (r & 1);
                C[m * 66 + n] += acc[t][r];
            }
        }
    }
    if (tid < DIMV) {
        float x0 = gx[tid];
        float l1 = gx[(size_t)(LSEQ - 1) * DIMV + tid] - x0;
        x0s[tid] = x0;
        l1s[tid] = l1;
        out[(size_t)b * OUTW + tid] = l1;            // level1
    }
    __syncthreads();

    // ---- areas: combine hi/lo blocks, antisymmetrize, correct, emit ----
#pragma unroll 1
    for (int q = tid; q < NPAIRS; q += THREADS) {
        float f = (63.0f - sqrtf((float)(3969 - 8 * q))) * 0.5f;
        int i = (int)f;
        int base = i * (63 - i) / 2;
        if (base > q) { i--; base = i * (63 - i) / 2; }
        else { int nb = (i + 1) * (62 - i) / 2; if (nb <= q) { i++; base = nb; } }
        int j = i + 1 + (q - base);
        float Cij = C[i * 66 + j] + C[i * 66 + j + 32]
                  + C[(i + 32) * 66 + j] + C[(i + 32) * 66 + j + 32];
        float Cji = C[j * 66 + i] + C[j * 66 + i + 32]
                  + C[(j + 32) * 66 + i] + C[(j + 32) * 66 + i + 32];
        out[(size_t)b * OUTW + DIMV + q] =
            0.5f * ((Cij - Cji) - x0s[i] * l1s[j] + x0s[j] * l1s[i]);
    }
}

extern "C" void kernel_launch(void* const* d_in, const int* in_sizes, int n_in,
                              void* d_out, int out_size) {
    const float* x = (const float*)d_in[0];
    float* out = (float*)d_out;
    const int B = in_sizes[0] / (LSEQ * DIMV);   // 512
    logsig_mma<<<B, THREADS>>>(x, out);
}